// round 2
// baseline (speedup 1.0000x reference)
#include <cuda_runtime.h>
#include <cstdint>

// Per-row top-k (k=64) of x[16384, 8192] fp32, scattered back densely.
// R2: warp-aggregated histogram atomics (__match_any_sync), shuffle-based
// suffix scan (4 barriers/round vs 16), and candidate compaction after
// round 0 so rounds 1-3 touch ~e<<8192 items instead of all 32 reg keys.

#define TPB   256
#define COLS  8192
#define VPT   8            // float4 per thread
#define EPT   32           // elements per thread
#define NWARP (TPB / 32)

__device__ __forceinline__ uint32_t f2key(float f) {
    uint32_t u = __float_as_uint(f);
    return u ^ ((u & 0x80000000u) ? 0xFFFFFFFFu : 0x80000000u);
}

__device__ __forceinline__ float key2f(uint32_t k) {
    uint32_t u = (k & 0x80000000u) ? (k ^ 0x80000000u) : ~k;
    return __uint_as_float(u);
}

__global__ void __launch_bounds__(TPB)
topk_scatter_kernel(const float* __restrict__ x,
                    const unsigned int* __restrict__ kp,
                    float* __restrict__ out)
{
    const int row  = blockIdx.x;
    const int t    = threadIdx.x;
    const int lane = t & 31;
    const int w    = t >> 5;

    const float4* __restrict__ xr   = reinterpret_cast<const float4*>(x + (size_t)row * COLS);
    float4* __restrict__       orow = reinterpret_cast<float4*>(out + (size_t)row * COLS);

    // ---- Load row into registers as radix keys (coalesced LDG.128) ----
    uint32_t key[EPT];
#pragma unroll
    for (int j = 0; j < VPT; j++) {
        float4 v = __ldg(&xr[t + j * TPB]);
        key[4*j + 0] = f2key(v.x);
        key[4*j + 1] = f2key(v.y);
        key[4*j + 2] = f2key(v.z);
        key[4*j + 3] = f2key(v.w);
    }

    __shared__ uint32_t hist[256];
    __shared__ uint32_t wsum[NWARP];
    __shared__ uint32_t buf[COLS];           // compacted candidate keys
    __shared__ uint32_t sh_sel, sh_hi, sh_e, sh_cnt;

    // k input (defensive parse; expected 64)
    uint32_t K = 64u;
    if (kp) {
        uint32_t raw = __ldg(kp);
        if (raw >= 1u && raw <= (uint32_t)COLS) {
            K = raw;
        } else {
            float f = __uint_as_float(raw);
            if (f >= 1.0f && f <= (float)COLS) K = (uint32_t)f;
        }
    }

    uint32_t kk = K;
    uint32_t prefix = 0;

    // ================= Round 0: top 8 bits, all 32 reg keys =================
    hist[t] = 0u;
    __syncthreads();

#pragma unroll
    for (int e = 0; e < EPT; e++) {
        uint32_t bin = key[e] >> 24;
        // warp-aggregated atomic: one ATOMS per distinct bin per warp
        unsigned m = __match_any_sync(0xFFFFFFFFu, bin);
        if ((unsigned)lane == (unsigned)(__ffs(m) - 1))
            atomicAdd(&hist[bin], (uint32_t)__popc(m));
    }
    __syncthreads();

    {
        // shuffle-based suffix scan: S[t] = sum_{j>=t} hist[j]
        uint32_t h = hist[t];
        uint32_t s = h;
#pragma unroll
        for (int off = 1; off < 32; off <<= 1) {
            uint32_t v = __shfl_down_sync(0xFFFFFFFFu, s, off);
            if (lane + off < 32) s += v;
        }
        if (lane == 0) wsum[w] = s;          // warp-total (suffix at lane 0)
        __syncthreads();
        uint32_t above = 0;
#pragma unroll
        for (int j = 0; j < NWARP; j++)
            if (j > w) above += wsum[j];
        uint32_t S = s + above;
        if (S >= kk && (S - h) < kk) {       // bin containing kk-th largest
            sh_sel = (uint32_t)t;
            sh_hi  = S - h;
            sh_e   = h;
        }
        __syncthreads();
    }

    prefix = sh_sel;
    kk    -= sh_hi;
    uint32_t e_cnt = sh_e;

    // ---- Compact round-0 survivors into shared buffer ----
    if (t == 0) sh_cnt = 0u;
    __syncthreads();
#pragma unroll
    for (int e = 0; e < EPT; e++) {
        uint32_t kv = key[e];
        if ((kv >> 24) == prefix)
            buf[atomicAdd(&sh_cnt, 1u)] = kv;
    }
    __syncthreads();

    // ================= Rounds 1-3: over compacted candidates =================
#pragma unroll
    for (int round = 1; round < 4; round++) {
        const int shift = 24 - 8 * round;
        const uint32_t pmask = 0xFFFFFFFFu << (shift + 8);
        const uint32_t phi   = prefix << (shift + 8);

        hist[t] = 0u;
        __syncthreads();

        for (uint32_t i = t; i < e_cnt; i += TPB) {
            uint32_t kv = buf[i];
            if ((kv & pmask) == phi)
                atomicAdd(&hist[(kv >> shift) & 0xFFu], 1u);
        }
        __syncthreads();

        uint32_t h = hist[t];
        uint32_t s = h;
#pragma unroll
        for (int off = 1; off < 32; off <<= 1) {
            uint32_t v = __shfl_down_sync(0xFFFFFFFFu, s, off);
            if (lane + off < 32) s += v;
        }
        if (lane == 0) wsum[w] = s;
        __syncthreads();
        uint32_t above = 0;
#pragma unroll
        for (int j = 0; j < NWARP; j++)
            if (j > w) above += wsum[j];
        uint32_t S = s + above;
        if (S >= kk && (S - h) < kk) {
            sh_sel = (uint32_t)t;
            sh_hi  = S - h;
            sh_e   = h;
        }
        __syncthreads();

        prefix = (prefix << 8) | sh_sel;
        kk    -= sh_hi;
        __syncthreads();   // protect sh_* / hist before next-round overwrite
    }

    const uint32_t thresh = prefix;   // exact K-th largest key
    const uint32_t keep   = kk;       // threshold-equal elements to keep
    const uint32_t neq    = sh_e;     // total threshold-equal elements

    // ---- Tie resolution (exact lowest-index-first semantics; rare path) ----
    int t_idx = COLS - 1;
    if (neq > keep) {
        int lo = 0, hi = COLS - 1;
        while (lo < hi) {
            int mid = (lo + hi) >> 1;
            if (t == 0) sh_cnt = 0u;
            __syncthreads();
            uint32_t local = 0;
#pragma unroll
            for (int j = 0; j < VPT; j++) {
                int base = 4 * (t + j * TPB);
#pragma unroll
                for (int c = 0; c < 4; c++) {
                    if (key[4*j + c] == thresh && (base + c) <= mid) local++;
                }
            }
            if (local) atomicAdd(&sh_cnt, local);
            __syncthreads();
            if (sh_cnt >= keep) hi = mid; else lo = mid + 1;
            __syncthreads();
        }
        t_idx = lo;
    }

    // ---- Write output (coalesced STG.128) ----
#pragma unroll
    for (int j = 0; j < VPT; j++) {
        const int base = 4 * (t + j * TPB);
        float4 o;
        {
            uint32_t kv = key[4*j + 0];
            o.x = (kv > thresh || (kv == thresh && (base + 0) <= t_idx)) ? key2f(kv) : 0.0f;
        }
        {
            uint32_t kv = key[4*j + 1];
            o.y = (kv > thresh || (kv == thresh && (base + 1) <= t_idx)) ? key2f(kv) : 0.0f;
        }
        {
            uint32_t kv = key[4*j + 2];
            o.z = (kv > thresh || (kv == thresh && (base + 2) <= t_idx)) ? key2f(kv) : 0.0f;
        }
        {
            uint32_t kv = key[4*j + 3];
            o.w = (kv > thresh || (kv == thresh && (base + 3) <= t_idx)) ? key2f(kv) : 0.0f;
        }
        orow[t + j * TPB] = o;
    }
}

extern "C" void kernel_launch(void* const* d_in, const int* in_sizes, int n_in,
                              void* d_out, int out_size)
{
    const float* x = (const float*)d_in[0];
    const unsigned int* kp = (n_in >= 2) ? (const unsigned int*)d_in[1] : nullptr;

    int rows = out_size / COLS;   // 16384
    topk_scatter_kernel<<<rows, TPB>>>(x, kp, (float*)d_out);
}